// round 14
// baseline (speedup 1.0000x reference)
#include <cuda_runtime.h>
#include <cuda_bf16.h>
#include <cstdint>

#define Bc 2
#define Hc 16
#define Sc 2048
#define Dc 64
#define NROWS (Bc * Hc * Sc)   // 65536
#define SP1 (Sc + 1)           // 2049
#define NT128 136              // 16*17/2 causal 128x128 tile pairs
#define NFILL 120              // 15*16/2 strictly-masked tile pairs

// Scratch
__device__ float g_invn[NROWS];    // log2e / ||k||
__device__ float g_rowsum[NROWS];  // sum of exps over lower triangle
__device__ float g_invz[NROWS];    // 1/Z
// Pre-split bf16 operands (hi/lo), K pre-scaled by log2e/||k||.
__device__ __nv_bfloat16 g_qh[NROWS * Dc];
__device__ __nv_bfloat16 g_ql[NROWS * Dc];
__device__ __nv_bfloat16 g_kh[NROWS * Dc];
__device__ __nv_bfloat16 g_kl[NROWS * Dc];

// ---------------------------------------------------------------------------
// helpers
// ---------------------------------------------------------------------------
__device__ __forceinline__ uint32_t smem_u32(const void* p) {
    uint32_t a;
    asm("{ .reg .u64 t; cvta.to.shared.u64 t, %1; cvt.u32.u64 %0, t; }" : "=r"(a) : "l"(p));
    return a;
}
__device__ __forceinline__ float ex2f(float x) {
    float r; asm("ex2.approx.f32 %0, %1;" : "=f"(r) : "f"(x)); return r;
}
__device__ __forceinline__ void stcs(float* p, float v) {
    asm volatile("st.global.cs.f32 [%0], %1;" :: "l"(p), "f"(v) : "memory");
}
__device__ __forceinline__ void stcs4(float* p, float v) {
    asm volatile("st.global.cs.v4.f32 [%0], {%1,%1,%1,%1};" :: "l"(p), "f"(v) : "memory");
}
__device__ __forceinline__ void ldsm_x4(uint32_t a, uint32_t& r0, uint32_t& r1,
                                        uint32_t& r2, uint32_t& r3) {
    asm volatile("ldmatrix.sync.aligned.m8n8.x4.shared.b16 {%0,%1,%2,%3}, [%4];"
                 : "=r"(r0), "=r"(r1), "=r"(r2), "=r"(r3) : "r"(a));
}
__device__ __forceinline__ void ldsm_x2(uint32_t a, uint32_t& r0, uint32_t& r1) {
    asm volatile("ldmatrix.sync.aligned.m8n8.x2.shared.b16 {%0,%1}, [%2];"
                 : "=r"(r0), "=r"(r1) : "r"(a));
}
__device__ __forceinline__ void mma_bf16(float* d, const uint32_t* a, const uint32_t* b) {
    asm volatile(
        "mma.sync.aligned.m16n8k16.row.col.f32.bf16.bf16.f32 "
        "{%0,%1,%2,%3}, {%4,%5,%6,%7}, {%8,%9}, {%0,%1,%2,%3};"
        : "+f"(d[0]), "+f"(d[1]), "+f"(d[2]), "+f"(d[3])
        : "r"(a[0]), "r"(a[1]), "r"(a[2]), "r"(a[3]), "r"(b[0]), "r"(b[1]));
}

// smem operand tiles: [128 rows][72 bf16] (144B padded rows)
#define TROW 72
#define TBYTES (128 * TROW * 2)          // 18432
#define OFF_QH 0
#define OFF_QL (1 * TBYTES)
#define OFF_KH (2 * TBYTES)
#define OFF_KL (3 * TBYTES)
#define SMEM_W (4 * TBYTES)              // 73728
#define SOFF_QH 0
#define SOFF_KH (1 * TBYTES)
#define SMEM_S (2 * TBYTES)              // 36864

// ---------------------------------------------------------------------------
// Kernel 1: per-key log2(e)/||k|| + zero row sums
// ---------------------------------------------------------------------------
__global__ __launch_bounds__(256) void prep_kernel(const float* __restrict__ k) {
    int row = blockIdx.x * blockDim.x + threadIdx.x;
    if (row >= NROWS) return;
    const float4* kr = (const float4*)(k + (size_t)row * Dc);
    float s = 0.f;
#pragma unroll
    for (int i = 0; i < Dc / 4; i++) {
        float4 v = kr[i];
        s += v.x * v.x + v.y * v.y + v.z * v.z + v.w * v.w;
    }
    g_invn[row] = 1.4426950408889634f * rsqrtf(s);
    g_rowsum[row] = 0.f;
}

// ---------------------------------------------------------------------------
// prep2: split Q and scaled-K into global bf16 hi/lo (once).
// ---------------------------------------------------------------------------
__global__ __launch_bounds__(256) void prep2_kernel(const float* __restrict__ q,
                                                    const float* __restrict__ k) {
    int rc = blockIdx.x * blockDim.x + threadIdx.x;   // 0 .. NROWS*16-1
    int row = rc >> 4, c4 = rc & 15;
    size_t eo = (size_t)row * Dc + c4 * 4;
    {
        float4 v = *(const float4*)(q + eo);
        union { __nv_bfloat16 b[4]; unsigned long long u; } H, L;
#pragma unroll
        for (int e = 0; e < 4; e++) {
            float x = (&v.x)[e];
            __nv_bfloat16 h = __float2bfloat16_rn(x);
            H.b[e] = h;
            L.b[e] = __float2bfloat16_rn(x - __bfloat162float(h));
        }
        *(unsigned long long*)(g_qh + eo) = H.u;
        *(unsigned long long*)(g_ql + eo) = L.u;
    }
    {
        float s = g_invn[row];
        float4 v = *(const float4*)(k + eo);
        union { __nv_bfloat16 b[4]; unsigned long long u; } H, L;
#pragma unroll
        for (int e = 0; e < 4; e++) {
            float x = (&v.x)[e] * s;
            __nv_bfloat16 h = __float2bfloat16_rn(x);
            H.b[e] = h;
            L.b[e] = __float2bfloat16_rn(x - __bfloat162float(h));
        }
        *(unsigned long long*)(g_kh + eo) = H.u;
        *(unsigned long long*)(g_kl + eo) = L.u;
    }
}

// ---------------------------------------------------------------------------
// staging helpers (16B copies from pre-split arrays)
// ---------------------------------------------------------------------------
__device__ __forceinline__ void stage2(char* smem, size_t base, int i0, int j0, int t) {
    const uint4* qh = (const uint4*)(g_qh + (base + i0) * Dc);
    const uint4* kh = (const uint4*)(g_kh + (base + j0) * Dc);
#pragma unroll
    for (int it = 0; it < 4; it++) {
        int idx = t + 256 * it;           // 0..1023
        int row = idx >> 3, ch = idx & 7;
        uint32_t so = (row * TROW + ch * 8) * 2;
        int gi = row * 8 + ch;
        *(uint4*)(smem + SOFF_QH + so) = qh[gi];
        *(uint4*)(smem + SOFF_KH + so) = kh[gi];
    }
}
__device__ __forceinline__ void stage4(char* smem, size_t base, int i0, int j0, int t) {
    const uint4* qh = (const uint4*)(g_qh + (base + i0) * Dc);
    const uint4* ql = (const uint4*)(g_ql + (base + i0) * Dc);
    const uint4* kh = (const uint4*)(g_kh + (base + j0) * Dc);
    const uint4* kl = (const uint4*)(g_kl + (base + j0) * Dc);
#pragma unroll
    for (int it = 0; it < 4; it++) {
        int idx = t + 256 * it;
        int row = idx >> 3, ch = idx & 7;
        uint32_t so = (row * TROW + ch * 8) * 2;
        int gi = row * 8 + ch;
        *(uint4*)(smem + OFF_QH + so) = qh[gi];
        *(uint4*)(smem + OFF_QL + so) = ql[gi];
        *(uint4*)(smem + OFF_KH + so) = kh[gi];
        *(uint4*)(smem + OFF_KL + so) = kl[gi];
    }
}

// One N-half GEMM, NPASS in {1,3}. acc[4][2][4] = 32 regs live.
template <int NPASS>
__device__ __forceinline__ void compute_half(uint32_t aHi, uint32_t aLo,
                                             uint32_t bHi, uint32_t bLo,
                                             int wm, int wn, int half,
                                             int lane, float acc[4][2][4]) {
#pragma unroll
    for (int mt = 0; mt < 4; mt++)
#pragma unroll
        for (int nt = 0; nt < 2; nt++)
#pragma unroll
            for (int e = 0; e < 4; e++) acc[mt][nt][e] = 0.f;

    const int a_row = (lane & 7) + ((lane >> 3) & 1) * 8;
    const int a_colb = (lane >> 4) * 8;
    const int b_row = lane & 7;
    const int b_colb = ((lane >> 3) & 1) * 8;
    const int ncol0 = wn * 32 + half * 16;

    const uint32_t aBases[3] = { aHi, aLo, aHi };
    const uint32_t bBases[3] = { bHi, bHi, bLo };

#pragma unroll
    for (int pass = 0; pass < NPASS; pass++) {
        const uint32_t aB = aBases[pass], bB = bBases[pass];
#pragma unroll
        for (int ks = 0; ks < 4; ks++) {
            uint32_t a[4][4], b[2][2];
#pragma unroll
            for (int mt = 0; mt < 4; mt++) {
                uint32_t addr = aB +
                    ((wm * 64 + mt * 16 + a_row) * TROW + ks * 16 + a_colb) * 2;
                ldsm_x4(addr, a[mt][0], a[mt][1], a[mt][2], a[mt][3]);
            }
#pragma unroll
            for (int nt = 0; nt < 2; nt++) {
                uint32_t addr = bB +
                    ((ncol0 + nt * 8 + b_row) * TROW + ks * 16 + b_colb) * 2;
                ldsm_x2(addr, b[nt][0], b[nt][1]);
            }
#pragma unroll
            for (int mt = 0; mt < 4; mt++)
#pragma unroll
                for (int nt = 0; nt < 2; nt++)
                    mma_bf16(acc[mt][nt], a[mt], b[nt]);
        }
    }
}

// triangular decode p -> (a, b), b <= a
__device__ __forceinline__ void tri_decode(int p, int& a, int& b) {
    a = (int)((sqrtf(8.0f * (float)p + 1.0f) - 1.0f) * 0.5f);
    while ((a + 1) * (a + 2) / 2 <= p) a++;
    while (a * (a + 1) / 2 > p) a--;
    b = p - a * (a + 1) / 2;
}

// ---------------------------------------------------------------------------
// Pass A: row sums, hi-only GEMM. 2 smem tiles, 3 CTAs/SM.
// ---------------------------------------------------------------------------
__global__ __launch_bounds__(256, 3) void sums_kernel() {
    extern __shared__ char smem[];
    const uint32_t sb = smem_u32(smem);
    const int t = threadIdx.x, wid = t >> 5, lane = t & 31;

    int qt, kt;
    tri_decode(blockIdx.x, qt, kt);
    const bool diag = (kt == qt);
    const int bh = blockIdx.y;
    const int i0 = qt * 128, j0 = kt * 128;
    const size_t base = (size_t)bh * Sc;

    stage2(smem, base, i0, j0, t);
    __syncthreads();

    const int wm = wid >> 2, wn = wid & 3;
    const int qrow = lane >> 2;
    const int cpair = (lane & 3) * 2;

    float rs0[4], rs1[4];
#pragma unroll
    for (int mt = 0; mt < 4; mt++) { rs0[mt] = 0.f; rs1[mt] = 0.f; }

#pragma unroll
    for (int half = 0; half < 2; half++) {
        float acc[4][2][4];
        compute_half<1>(sb + SOFF_QH, 0u, sb + SOFF_KH, 0u, wm, wn, half, lane, acc);
#pragma unroll
        for (int mt = 0; mt < 4; mt++) {
            const int r0l = wm * 64 + mt * 16 + qrow;
            const int r1l = r0l + 8;
#pragma unroll
            for (int nt = 0; nt < 2; nt++) {
                const int c = wn * 32 + half * 16 + nt * 8 + cpair;
                float* d = acc[mt][nt];
                if (!diag || c <= r0l)     rs0[mt] += ex2f(d[0]);
                if (!diag || c + 1 <= r0l) rs0[mt] += ex2f(d[1]);
                if (!diag || c <= r1l)     rs1[mt] += ex2f(d[2]);
                if (!diag || c + 1 <= r1l) rs1[mt] += ex2f(d[3]);
            }
        }
    }

#pragma unroll
    for (int mt = 0; mt < 4; mt++) {
        const int r0l = wm * 64 + mt * 16 + qrow;
        float s0 = rs0[mt], s1 = rs1[mt];
        s0 += __shfl_xor_sync(0xffffffffu, s0, 1);
        s0 += __shfl_xor_sync(0xffffffffu, s0, 2);
        s1 += __shfl_xor_sync(0xffffffffu, s1, 1);
        s1 += __shfl_xor_sync(0xffffffffu, s1, 2);
        if ((lane & 3) == 0) {
            atomicAdd(&g_rowsum[base + i0 + r0l], s0);
            atomicAdd(&g_rowsum[base + i0 + r0l + 8], s1);
        }
    }
}

// ---------------------------------------------------------------------------
// zfin: invZ per row + write the sink column of out.
// ---------------------------------------------------------------------------
__global__ __launch_bounds__(256) void zfin_kernel(const float* __restrict__ sinks,
                                                   float* __restrict__ out) {
    int row = blockIdx.x * blockDim.x + threadIdx.x;
    if (row >= NROWS) return;
    const int i = row & (Sc - 1);
    const float es = __expf(sinks[row]);
    const float invZ = 1.0f / (g_rowsum[row] + (float)(Sc - 1 - i) + es);
    g_invz[row] = invZ;
    out[(size_t)row * SP1 + Sc] = es * invZ;
}

// ---------------------------------------------------------------------------
// Fill kernel: strictly-masked tiles (kt > qt), out = invZ.
// ---------------------------------------------------------------------------
__global__ __launch_bounds__(256) void fill_kernel(float* __restrict__ out) {
    int a, b;
    tri_decode(blockIdx.x, a, b);
    const int kt = a + 1;
    const int qt = b;
    const int bh = blockIdx.y;
    const int i0 = qt * 128, j0 = kt * 128;
    const size_t base = (size_t)bh * Sc;
    const int wid = threadIdx.x >> 5, lane = threadIdx.x & 31;

#pragma unroll
    for (int rr = 0; rr < 16; rr++) {
        const int r = wid * 16 + rr;
        const size_t rowg = base + i0 + r;
        const float invZ = g_invz[rowg];
        const size_t g0 = rowg * SP1 + j0;
        float* rp = out + g0;
        const int a0 = ((int)(4 - (g0 & 3))) & 3;
        const int nvec = (128 - a0) >> 2;
        if (lane < a0) stcs(rp + lane, invZ);
        if (lane < nvec) stcs4(rp + a0 + 4 * lane, invZ);
        if (lane == 31 && a0) {
#pragma unroll
            for (int ti = 0; ti < 3; ti++)
                if (ti < 4 - a0) stcs(rp + a0 + 124 + ti, invZ);
        }
    }
}

// ---------------------------------------------------------------------------
// Pass B: causal tiles. Full 3-pass GEMM, direct fragment stores (R12 style),
// now at 3 CTAs/SM (smem 3*73728 = 221184 fits; reg cap 84).
// ---------------------------------------------------------------------------
__global__ __launch_bounds__(256, 3) void write_kernel(float* __restrict__ out) {
    extern __shared__ char smem[];
    const uint32_t sb = smem_u32(smem);
    const int t = threadIdx.x, wid = t >> 5, lane = t & 31;

    int qt, kt;
    tri_decode(blockIdx.x, qt, kt);
    const bool diag = (kt == qt);
    const int bh = blockIdx.y;
    const int i0 = qt * 128, j0 = kt * 128;
    const size_t base = (size_t)bh * Sc;

    stage4(smem, base, i0, j0, t);
    __syncthreads();

    const int wm = wid >> 2, wn = wid & 3;
    const int qrow = lane >> 2;
    const int cpair = (lane & 3) * 2;

#pragma unroll
    for (int half = 0; half < 2; half++) {
        float acc[4][2][4];
        compute_half<3>(sb + OFF_QH, sb + OFF_QL, sb + OFF_KH, sb + OFF_KL,
                        wm, wn, half, lane, acc);
#pragma unroll
        for (int mt = 0; mt < 4; mt++) {
            const int r0l = wm * 64 + mt * 16 + qrow;
            const int r1l = r0l + 8;
            const float iz0 = g_invz[base + i0 + r0l];
            const float iz1 = g_invz[base + i0 + r1l];
            float* orow0 = out + (base + (size_t)(i0 + r0l)) * SP1 + j0;
            float* orow1 = out + (base + (size_t)(i0 + r1l)) * SP1 + j0;
#pragma unroll
            for (int nt = 0; nt < 2; nt++) {
                const int c = wn * 32 + half * 16 + nt * 8 + cpair;
                float* d = acc[mt][nt];
                stcs(orow0 + c,     (!diag || c <= r0l)     ? ex2f(d[0]) * iz0 : iz0);
                stcs(orow0 + c + 1, (!diag || c + 1 <= r0l) ? ex2f(d[1]) * iz0 : iz0);
                stcs(orow1 + c,     (!diag || c <= r1l)     ? ex2f(d[2]) * iz1 : iz1);
                stcs(orow1 + c + 1, (!diag || c + 1 <= r1l) ? ex2f(d[3]) * iz1 : iz1);
            }
        }
    }
}

// ---------------------------------------------------------------------------
extern "C" void kernel_launch(void* const* d_in, const int* in_sizes, int n_in,
                              void* d_out, int out_size) {
    const float* q     = (const float*)d_in[0];
    const float* k     = (const float*)d_in[1];
    const float* sinks = (const float*)d_in[2];
    float* out = (float*)d_out;
    (void)in_sizes; (void)n_in; (void)out_size;

    cudaFuncSetAttribute(sums_kernel, cudaFuncAttributeMaxDynamicSharedMemorySize, SMEM_S);
    cudaFuncSetAttribute(write_kernel, cudaFuncAttributeMaxDynamicSharedMemorySize, SMEM_W);

    prep_kernel<<<NROWS / 256, 256>>>(k);
    prep2_kernel<<<NROWS * 16 / 256, 256>>>(q, k);
    sums_kernel<<<dim3(NT128, Bc * Hc), 256, SMEM_S>>>();
    zfin_kernel<<<NROWS / 256, 256>>>(sinks, out);
    fill_kernel<<<dim3(NFILL, Bc * Hc), 256>>>(out);
    write_kernel<<<dim3(NT128, Bc * Hc), 256, SMEM_W>>>(out);
}

// round 15
// speedup vs baseline: 1.1131x; 1.1131x over previous
#include <cuda_runtime.h>
#include <cuda_bf16.h>
#include <cstdint>

#define Bc 2
#define Hc 16
#define Sc 2048
#define Dc 64
#define NROWS (Bc * Hc * Sc)   // 65536
#define SP1 (Sc + 1)           // 2049
#define NT128 136              // 16*17/2 causal 128x128 tile pairs
#define NFILL 120              // 15*16/2 strictly-masked tile pairs

// Scratch
__device__ float g_invn[NROWS];    // log2e / ||k||
__device__ float g_rowsum[NROWS];  // sum of exps over lower triangle
__device__ float g_invz[NROWS];    // 1/Z
// Pre-split bf16 operands (hi/lo), K pre-scaled by log2e/||k||.
__device__ __nv_bfloat16 g_qh[NROWS * Dc];
__device__ __nv_bfloat16 g_ql[NROWS * Dc];
__device__ __nv_bfloat16 g_kh[NROWS * Dc];
__device__ __nv_bfloat16 g_kl[NROWS * Dc];

// ---------------------------------------------------------------------------
// helpers
// ---------------------------------------------------------------------------
__device__ __forceinline__ uint32_t smem_u32(const void* p) {
    uint32_t a;
    asm("{ .reg .u64 t; cvta.to.shared.u64 t, %1; cvt.u32.u64 %0, t; }" : "=r"(a) : "l"(p));
    return a;
}
__device__ __forceinline__ float ex2f(float x) {
    float r; asm("ex2.approx.f32 %0, %1;" : "=f"(r) : "f"(x)); return r;
}
__device__ __forceinline__ void stcs(float* p, float v) {
    asm volatile("st.global.cs.f32 [%0], %1;" :: "l"(p), "f"(v) : "memory");
}
__device__ __forceinline__ void stcs4(float* p, float v) {
    asm volatile("st.global.cs.v4.f32 [%0], {%1,%1,%1,%1};" :: "l"(p), "f"(v) : "memory");
}
__device__ __forceinline__ void ldsm_x4(uint32_t a, uint32_t& r0, uint32_t& r1,
                                        uint32_t& r2, uint32_t& r3) {
    asm volatile("ldmatrix.sync.aligned.m8n8.x4.shared.b16 {%0,%1,%2,%3}, [%4];"
                 : "=r"(r0), "=r"(r1), "=r"(r2), "=r"(r3) : "r"(a));
}
__device__ __forceinline__ void ldsm_x2(uint32_t a, uint32_t& r0, uint32_t& r1) {
    asm volatile("ldmatrix.sync.aligned.m8n8.x2.shared.b16 {%0,%1}, [%2];"
                 : "=r"(r0), "=r"(r1) : "r"(a));
}
__device__ __forceinline__ void mma_bf16(float* d, const uint32_t* a, const uint32_t* b) {
    asm volatile(
        "mma.sync.aligned.m16n8k16.row.col.f32.bf16.bf16.f32 "
        "{%0,%1,%2,%3}, {%4,%5,%6,%7}, {%8,%9}, {%0,%1,%2,%3};"
        : "+f"(d[0]), "+f"(d[1]), "+f"(d[2]), "+f"(d[3])
        : "r"(a[0]), "r"(a[1]), "r"(a[2]), "r"(a[3]), "r"(b[0]), "r"(b[1]));
}

// smem operand tiles: [128 rows][72 bf16] (144B padded rows)
#define TROW 72
#define TBYTES (128 * TROW * 2)          // 18432
#define OFF_QH 0
#define OFF_QL (1 * TBYTES)
#define OFF_KH (2 * TBYTES)
#define OFF_KL (3 * TBYTES)
#define SMEM_W (4 * TBYTES)              // 73728
#define SOFF_QH 0
#define SOFF_KH (1 * TBYTES)
#define SMEM_S (2 * TBYTES)              // 36864

// ---------------------------------------------------------------------------
// Kernel 1: per-key log2(e)/||k|| + zero row sums
// ---------------------------------------------------------------------------
__global__ __launch_bounds__(256) void prep_kernel(const float* __restrict__ k) {
    int row = blockIdx.x * blockDim.x + threadIdx.x;
    if (row >= NROWS) return;
    const float4* kr = (const float4*)(k + (size_t)row * Dc);
    float s = 0.f;
#pragma unroll
    for (int i = 0; i < Dc / 4; i++) {
        float4 v = kr[i];
        s += v.x * v.x + v.y * v.y + v.z * v.z + v.w * v.w;
    }
    g_invn[row] = 1.4426950408889634f * rsqrtf(s);
    g_rowsum[row] = 0.f;
}

// ---------------------------------------------------------------------------
// prep2: split Q and scaled-K into global bf16 hi/lo (once).
// ---------------------------------------------------------------------------
__global__ __launch_bounds__(256) void prep2_kernel(const float* __restrict__ q,
                                                    const float* __restrict__ k) {
    int rc = blockIdx.x * blockDim.x + threadIdx.x;   // 0 .. NROWS*16-1
    int row = rc >> 4, c4 = rc & 15;
    size_t eo = (size_t)row * Dc + c4 * 4;
    {
        float4 v = *(const float4*)(q + eo);
        union { __nv_bfloat16 b[4]; unsigned long long u; } H, L;
#pragma unroll
        for (int e = 0; e < 4; e++) {
            float x = (&v.x)[e];
            __nv_bfloat16 h = __float2bfloat16_rn(x);
            H.b[e] = h;
            L.b[e] = __float2bfloat16_rn(x - __bfloat162float(h));
        }
        *(unsigned long long*)(g_qh + eo) = H.u;
        *(unsigned long long*)(g_ql + eo) = L.u;
    }
    {
        float s = g_invn[row];
        float4 v = *(const float4*)(k + eo);
        union { __nv_bfloat16 b[4]; unsigned long long u; } H, L;
#pragma unroll
        for (int e = 0; e < 4; e++) {
            float x = (&v.x)[e] * s;
            __nv_bfloat16 h = __float2bfloat16_rn(x);
            H.b[e] = h;
            L.b[e] = __float2bfloat16_rn(x - __bfloat162float(h));
        }
        *(unsigned long long*)(g_kh + eo) = H.u;
        *(unsigned long long*)(g_kl + eo) = L.u;
    }
}

// ---------------------------------------------------------------------------
// staging helpers (16B copies from pre-split arrays)
// ---------------------------------------------------------------------------
__device__ __forceinline__ void stage2(char* smem, size_t base, int i0, int j0, int t) {
    const uint4* qh = (const uint4*)(g_qh + (base + i0) * Dc);
    const uint4* kh = (const uint4*)(g_kh + (base + j0) * Dc);
#pragma unroll
    for (int it = 0; it < 4; it++) {
        int idx = t + 256 * it;           // 0..1023
        int row = idx >> 3, ch = idx & 7;
        uint32_t so = (row * TROW + ch * 8) * 2;
        int gi = row * 8 + ch;
        *(uint4*)(smem + SOFF_QH + so) = qh[gi];
        *(uint4*)(smem + SOFF_KH + so) = kh[gi];
    }
}
__device__ __forceinline__ void stage4(char* smem, size_t base, int i0, int j0, int t) {
    const uint4* qh = (const uint4*)(g_qh + (base + i0) * Dc);
    const uint4* ql = (const uint4*)(g_ql + (base + i0) * Dc);
    const uint4* kh = (const uint4*)(g_kh + (base + j0) * Dc);
    const uint4* kl = (const uint4*)(g_kl + (base + j0) * Dc);
#pragma unroll
    for (int it = 0; it < 4; it++) {
        int idx = t + 256 * it;
        int row = idx >> 3, ch = idx & 7;
        uint32_t so = (row * TROW + ch * 8) * 2;
        int gi = row * 8 + ch;
        *(uint4*)(smem + OFF_QH + so) = qh[gi];
        *(uint4*)(smem + OFF_QL + so) = ql[gi];
        *(uint4*)(smem + OFF_KH + so) = kh[gi];
        *(uint4*)(smem + OFF_KL + so) = kl[gi];
    }
}

// One N-half GEMM, NPASS in {1,3}. acc[4][2][4] = 32 regs live.
template <int NPASS>
__device__ __forceinline__ void compute_half(uint32_t aHi, uint32_t aLo,
                                             uint32_t bHi, uint32_t bLo,
                                             int wm, int wn, int half,
                                             int lane, float acc[4][2][4]) {
#pragma unroll
    for (int mt = 0; mt < 4; mt++)
#pragma unroll
        for (int nt = 0; nt < 2; nt++)
#pragma unroll
            for (int e = 0; e < 4; e++) acc[mt][nt][e] = 0.f;

    const int a_row = (lane & 7) + ((lane >> 3) & 1) * 8;
    const int a_colb = (lane >> 4) * 8;
    const int b_row = lane & 7;
    const int b_colb = ((lane >> 3) & 1) * 8;
    const int ncol0 = wn * 32 + half * 16;

    const uint32_t aBases[3] = { aHi, aLo, aHi };
    const uint32_t bBases[3] = { bHi, bHi, bLo };

#pragma unroll
    for (int pass = 0; pass < NPASS; pass++) {
        const uint32_t aB = aBases[pass], bB = bBases[pass];
#pragma unroll
        for (int ks = 0; ks < 4; ks++) {
            uint32_t a[4][4], b[2][2];
#pragma unroll
            for (int mt = 0; mt < 4; mt++) {
                uint32_t addr = aB +
                    ((wm * 64 + mt * 16 + a_row) * TROW + ks * 16 + a_colb) * 2;
                ldsm_x4(addr, a[mt][0], a[mt][1], a[mt][2], a[mt][3]);
            }
#pragma unroll
            for (int nt = 0; nt < 2; nt++) {
                uint32_t addr = bB +
                    ((ncol0 + nt * 8 + b_row) * TROW + ks * 16 + b_colb) * 2;
                ldsm_x2(addr, b[nt][0], b[nt][1]);
            }
#pragma unroll
            for (int mt = 0; mt < 4; mt++)
#pragma unroll
                for (int nt = 0; nt < 2; nt++)
                    mma_bf16(acc[mt][nt], a[mt], b[nt]);
        }
    }
}

// triangular decode p -> (a, b), b <= a
__device__ __forceinline__ void tri_decode(int p, int& a, int& b) {
    a = (int)((sqrtf(8.0f * (float)p + 1.0f) - 1.0f) * 0.5f);
    while ((a + 1) * (a + 2) / 2 <= p) a++;
    while (a * (a + 1) / 2 > p) a--;
    b = p - a * (a + 1) / 2;
}

// ---------------------------------------------------------------------------
// Pass A: row sums, hi-only GEMM. 2 smem tiles, 3 CTAs/SM. Uniform diag branch.
// ---------------------------------------------------------------------------
__global__ __launch_bounds__(256, 3) void sums_kernel() {
    extern __shared__ char smem[];
    const uint32_t sb = smem_u32(smem);
    const int t = threadIdx.x, wid = t >> 5, lane = t & 31;

    int qt, kt;
    tri_decode(blockIdx.x, qt, kt);
    const bool diag = (kt == qt);
    const int bh = blockIdx.y;
    const int i0 = qt * 128, j0 = kt * 128;
    const size_t base = (size_t)bh * Sc;

    stage2(smem, base, i0, j0, t);
    __syncthreads();

    const int wm = wid >> 2, wn = wid & 3;
    const int qrow = lane >> 2;
    const int cpair = (lane & 3) * 2;

    float rs0[4], rs1[4];
#pragma unroll
    for (int mt = 0; mt < 4; mt++) { rs0[mt] = 0.f; rs1[mt] = 0.f; }

#pragma unroll
    for (int half = 0; half < 2; half++) {
        float acc[4][2][4];
        compute_half<1>(sb + SOFF_QH, 0u, sb + SOFF_KH, 0u, wm, wn, half, lane, acc);
        if (!diag) {
#pragma unroll
            for (int mt = 0; mt < 4; mt++)
#pragma unroll
                for (int nt = 0; nt < 2; nt++) {
                    float* d = acc[mt][nt];
                    rs0[mt] += ex2f(d[0]) + ex2f(d[1]);
                    rs1[mt] += ex2f(d[2]) + ex2f(d[3]);
                }
        } else {
#pragma unroll
            for (int mt = 0; mt < 4; mt++) {
                const int r0l = wm * 64 + mt * 16 + qrow;
                const int r1l = r0l + 8;
#pragma unroll
                for (int nt = 0; nt < 2; nt++) {
                    const int c = wn * 32 + half * 16 + nt * 8 + cpair;
                    float* d = acc[mt][nt];
                    if (c <= r0l)     rs0[mt] += ex2f(d[0]);
                    if (c + 1 <= r0l) rs0[mt] += ex2f(d[1]);
                    if (c <= r1l)     rs1[mt] += ex2f(d[2]);
                    if (c + 1 <= r1l) rs1[mt] += ex2f(d[3]);
                }
            }
        }
    }

#pragma unroll
    for (int mt = 0; mt < 4; mt++) {
        const int r0l = wm * 64 + mt * 16 + qrow;
        float s0 = rs0[mt], s1 = rs1[mt];
        s0 += __shfl_xor_sync(0xffffffffu, s0, 1);
        s0 += __shfl_xor_sync(0xffffffffu, s0, 2);
        s1 += __shfl_xor_sync(0xffffffffu, s1, 1);
        s1 += __shfl_xor_sync(0xffffffffu, s1, 2);
        if ((lane & 3) == 0) {
            atomicAdd(&g_rowsum[base + i0 + r0l], s0);
            atomicAdd(&g_rowsum[base + i0 + r0l + 8], s1);
        }
    }
}

// ---------------------------------------------------------------------------
// zfin: invZ per row + write the sink column of out.
// ---------------------------------------------------------------------------
__global__ __launch_bounds__(256) void zfin_kernel(const float* __restrict__ sinks,
                                                   float* __restrict__ out) {
    int row = blockIdx.x * blockDim.x + threadIdx.x;
    if (row >= NROWS) return;
    const int i = row & (Sc - 1);
    const float es = __expf(sinks[row]);
    const float invZ = 1.0f / (g_rowsum[row] + (float)(Sc - 1 - i) + es);
    g_invz[row] = invZ;
    out[(size_t)row * SP1 + Sc] = es * invZ;
}

// ---------------------------------------------------------------------------
// Fill kernel: strictly-masked tiles (kt > qt), out = invZ.
// ---------------------------------------------------------------------------
__global__ __launch_bounds__(256) void fill_kernel(float* __restrict__ out) {
    int a, b;
    tri_decode(blockIdx.x, a, b);
    const int kt = a + 1;
    const int qt = b;
    const int bh = blockIdx.y;
    const int i0 = qt * 128, j0 = kt * 128;
    const size_t base = (size_t)bh * Sc;
    const int wid = threadIdx.x >> 5, lane = threadIdx.x & 31;

#pragma unroll
    for (int rr = 0; rr < 16; rr++) {
        const int r = wid * 16 + rr;
        const size_t rowg = base + i0 + r;
        const float invZ = g_invz[rowg];
        const size_t g0 = rowg * SP1 + j0;
        float* rp = out + g0;
        const int a0 = ((int)(4 - (g0 & 3))) & 3;
        const int nvec = (128 - a0) >> 2;
        if (lane < a0) stcs(rp + lane, invZ);
        if (lane < nvec) stcs4(rp + a0 + 4 * lane, invZ);
        if (lane == 31 && a0) {
#pragma unroll
            for (int ti = 0; ti < 3; ti++)
                if (ti < 4 - a0) stcs(rp + a0 + 124 + ti, invZ);
        }
    }
}

// ---------------------------------------------------------------------------
// Pass B: causal tiles. Full 3-pass GEMM, direct fragment stores, 2 CTAs/SM
// (R12 config). Uniform diag branch removes per-element predicates on 120/136
// tiles.
// ---------------------------------------------------------------------------
__global__ __launch_bounds__(256, 2) void write_kernel(float* __restrict__ out) {
    extern __shared__ char smem[];
    const uint32_t sb = smem_u32(smem);
    const int t = threadIdx.x, wid = t >> 5, lane = t & 31;

    int qt, kt;
    tri_decode(blockIdx.x, qt, kt);
    const bool diag = (kt == qt);
    const int bh = blockIdx.y;
    const int i0 = qt * 128, j0 = kt * 128;
    const size_t base = (size_t)bh * Sc;

    stage4(smem, base, i0, j0, t);
    __syncthreads();

    const int wm = wid >> 2, wn = wid & 3;
    const int qrow = lane >> 2;
    const int cpair = (lane & 3) * 2;

#pragma unroll
    for (int half = 0; half < 2; half++) {
        float acc[4][2][4];
        compute_half<3>(sb + OFF_QH, sb + OFF_QL, sb + OFF_KH, sb + OFF_KL,
                        wm, wn, half, lane, acc);
#pragma unroll
        for (int mt = 0; mt < 4; mt++) {
            const int r0l = wm * 64 + mt * 16 + qrow;
            const int r1l = r0l + 8;
            const float iz0 = g_invz[base + i0 + r0l];
            const float iz1 = g_invz[base + i0 + r1l];
            float* orow0 = out + (base + (size_t)(i0 + r0l)) * SP1 + j0;
            float* orow1 = out + (base + (size_t)(i0 + r1l)) * SP1 + j0;
            if (!diag) {
#pragma unroll
                for (int nt = 0; nt < 2; nt++) {
                    const int c = wn * 32 + half * 16 + nt * 8 + cpair;
                    float* d = acc[mt][nt];
                    stcs(orow0 + c,     ex2f(d[0]) * iz0);
                    stcs(orow0 + c + 1, ex2f(d[1]) * iz0);
                    stcs(orow1 + c,     ex2f(d[2]) * iz1);
                    stcs(orow1 + c + 1, ex2f(d[3]) * iz1);
                }
            } else {
#pragma unroll
                for (int nt = 0; nt < 2; nt++) {
                    const int c = wn * 32 + half * 16 + nt * 8 + cpair;
                    float* d = acc[mt][nt];
                    stcs(orow0 + c,     (c <= r0l)     ? ex2f(d[0]) * iz0 : iz0);
                    stcs(orow0 + c + 1, (c + 1 <= r0l) ? ex2f(d[1]) * iz0 : iz0);
                    stcs(orow1 + c,     (c <= r1l)     ? ex2f(d[2]) * iz1 : iz1);
                    stcs(orow1 + c + 1, (c + 1 <= r1l) ? ex2f(d[3]) * iz1 : iz1);
                }
            }
        }
    }
}

// ---------------------------------------------------------------------------
extern "C" void kernel_launch(void* const* d_in, const int* in_sizes, int n_in,
                              void* d_out, int out_size) {
    const float* q     = (const float*)d_in[0];
    const float* k     = (const float*)d_in[1];
    const float* sinks = (const float*)d_in[2];
    float* out = (float*)d_out;
    (void)in_sizes; (void)n_in; (void)out_size;

    // Host-side resources, created once on the (non-captured) correctness call.
    static cudaStream_t s2 = nullptr;
    static cudaEvent_t evA = nullptr, evB = nullptr;
    if (s2 == nullptr) {
        cudaStreamCreateWithFlags(&s2, cudaStreamNonBlocking);
        cudaEventCreateWithFlags(&evA, cudaEventDisableTiming);
        cudaEventCreateWithFlags(&evB, cudaEventDisableTiming);
        cudaFuncSetAttribute(sums_kernel, cudaFuncAttributeMaxDynamicSharedMemorySize, SMEM_S);
        cudaFuncSetAttribute(write_kernel, cudaFuncAttributeMaxDynamicSharedMemorySize, SMEM_W);
    }

    prep_kernel<<<NROWS / 256, 256>>>(k);
    prep2_kernel<<<NROWS * 16 / 256, 256>>>(q, k);
    sums_kernel<<<dim3(NT128, Bc * Hc), 256, SMEM_S>>>();
    zfin_kernel<<<NROWS / 256, 256>>>(sinks, out);

    // Fork: fill (DRAM-heavy) runs concurrently with write (compute-heavy).
    cudaEventRecord(evA, 0);
    cudaStreamWaitEvent(s2, evA, 0);
    fill_kernel<<<dim3(NFILL, Bc * Hc), 256, 0, s2>>>(out);
    cudaEventRecord(evB, s2);

    write_kernel<<<dim3(NT128, Bc * Hc), 256, SMEM_W>>>(out);
    cudaStreamWaitEvent(0, evB, 0);
}

// round 16
// speedup vs baseline: 1.1321x; 1.0170x over previous
#include <cuda_runtime.h>
#include <cuda_bf16.h>
#include <cstdint>

#define Bc 2
#define Hc 16
#define Sc 2048
#define Dc 64
#define NROWS (Bc * Hc * Sc)   // 65536
#define SP1 (Sc + 1)           // 2049
#define NT128 136              // 16*17/2 causal 128x128 tile pairs
#define NFILL 120              // 15*16/2 strictly-masked tile pairs

// Scratch
__device__ float g_rowsum[NROWS];  // sum of exps over lower triangle
__device__ float g_invz[NROWS];    // 1/Z
// Pre-split bf16 operands (hi/lo), K pre-scaled by log2e/||k||.
__device__ __nv_bfloat16 g_qh[NROWS * Dc];
__device__ __nv_bfloat16 g_ql[NROWS * Dc];
__device__ __nv_bfloat16 g_kh[NROWS * Dc];
__device__ __nv_bfloat16 g_kl[NROWS * Dc];

// ---------------------------------------------------------------------------
// helpers
// ---------------------------------------------------------------------------
__device__ __forceinline__ uint32_t smem_u32(const void* p) {
    uint32_t a;
    asm("{ .reg .u64 t; cvta.to.shared.u64 t, %1; cvt.u32.u64 %0, t; }" : "=r"(a) : "l"(p));
    return a;
}
__device__ __forceinline__ float ex2f(float x) {
    float r; asm("ex2.approx.f32 %0, %1;" : "=f"(r) : "f"(x)); return r;
}
__device__ __forceinline__ void stcs(float* p, float v) {
    asm volatile("st.global.cs.f32 [%0], %1;" :: "l"(p), "f"(v) : "memory");
}
__device__ __forceinline__ void stcs4(float* p, float v) {
    asm volatile("st.global.cs.v4.f32 [%0], {%1,%1,%1,%1};" :: "l"(p), "f"(v) : "memory");
}
__device__ __forceinline__ void ldsm_x4(uint32_t a, uint32_t& r0, uint32_t& r1,
                                        uint32_t& r2, uint32_t& r3) {
    asm volatile("ldmatrix.sync.aligned.m8n8.x4.shared.b16 {%0,%1,%2,%3}, [%4];"
                 : "=r"(r0), "=r"(r1), "=r"(r2), "=r"(r3) : "r"(a));
}
__device__ __forceinline__ void ldsm_x2(uint32_t a, uint32_t& r0, uint32_t& r1) {
    asm volatile("ldmatrix.sync.aligned.m8n8.x2.shared.b16 {%0,%1}, [%2];"
                 : "=r"(r0), "=r"(r1) : "r"(a));
}
__device__ __forceinline__ void mma_bf16(float* d, const uint32_t* a, const uint32_t* b) {
    asm volatile(
        "mma.sync.aligned.m16n8k16.row.col.f32.bf16.bf16.f32 "
        "{%0,%1,%2,%3}, {%4,%5,%6,%7}, {%8,%9}, {%0,%1,%2,%3};"
        : "+f"(d[0]), "+f"(d[1]), "+f"(d[2]), "+f"(d[3])
        : "r"(a[0]), "r"(a[1]), "r"(a[2]), "r"(a[3]), "r"(b[0]), "r"(b[1]));
}

// smem operand tiles: [128 rows][72 bf16] (144B padded rows)
#define TROW 72
#define TBYTES (128 * TROW * 2)          // 18432
#define OFF_QH 0
#define OFF_QL (1 * TBYTES)
#define OFF_KH (2 * TBYTES)
#define OFF_KL (3 * TBYTES)
#define SMEM_W (4 * TBYTES)              // 73728
#define SOFF_QH 0
#define SOFF_KH (1 * TBYTES)
#define SMEM_S (2 * TBYTES)              // 36864

// ---------------------------------------------------------------------------
// prep2: fused norm + bf16 hi/lo split. One warp handles 2 rows (16 lanes per
// row, lane c4 = lane&15 owns one float4 chunk). ||k||^2 reduced across the
// 16-lane half via butterfly shuffles; invn = log2e * rsqrt computed locally.
// Also zeroes g_rowsum.
// ---------------------------------------------------------------------------
__global__ __launch_bounds__(256) void prep2_kernel(const float* __restrict__ q,
                                                    const float* __restrict__ k) {
    const int t = threadIdx.x;
    const int wid = t >> 5, lane = t & 31;
    const int row = blockIdx.x * 16 + wid * 2 + (lane >> 4);
    const int c4 = lane & 15;
    const size_t eo = (size_t)row * Dc + c4 * 4;

    // k norm: partial sumsq + 16-lane butterfly
    float4 kv = *(const float4*)(k + eo);
    float ss = kv.x * kv.x + kv.y * kv.y + kv.z * kv.z + kv.w * kv.w;
    ss += __shfl_xor_sync(0xffffffffu, ss, 1);
    ss += __shfl_xor_sync(0xffffffffu, ss, 2);
    ss += __shfl_xor_sync(0xffffffffu, ss, 4);
    ss += __shfl_xor_sync(0xffffffffu, ss, 8);
    const float s = 1.4426950408889634f * rsqrtf(ss);

    if (c4 == 0) g_rowsum[row] = 0.f;

    {
        float4 v = *(const float4*)(q + eo);
        union { __nv_bfloat16 b[4]; unsigned long long u; } H, L;
#pragma unroll
        for (int e = 0; e < 4; e++) {
            float x = (&v.x)[e];
            __nv_bfloat16 h = __float2bfloat16_rn(x);
            H.b[e] = h;
            L.b[e] = __float2bfloat16_rn(x - __bfloat162float(h));
        }
        *(unsigned long long*)(g_qh + eo) = H.u;
        *(unsigned long long*)(g_ql + eo) = L.u;
    }
    {
        union { __nv_bfloat16 b[4]; unsigned long long u; } H, L;
#pragma unroll
        for (int e = 0; e < 4; e++) {
            float x = (&kv.x)[e] * s;
            __nv_bfloat16 h = __float2bfloat16_rn(x);
            H.b[e] = h;
            L.b[e] = __float2bfloat16_rn(x - __bfloat162float(h));
        }
        *(unsigned long long*)(g_kh + eo) = H.u;
        *(unsigned long long*)(g_kl + eo) = L.u;
    }
}

// ---------------------------------------------------------------------------
// staging helpers (16B copies from pre-split arrays)
// ---------------------------------------------------------------------------
__device__ __forceinline__ void stage2(char* smem, size_t base, int i0, int j0, int t) {
    const uint4* qh = (const uint4*)(g_qh + (base + i0) * Dc);
    const uint4* kh = (const uint4*)(g_kh + (base + j0) * Dc);
#pragma unroll
    for (int it = 0; it < 4; it++) {
        int idx = t + 256 * it;           // 0..1023
        int row = idx >> 3, ch = idx & 7;
        uint32_t so = (row * TROW + ch * 8) * 2;
        int gi = row * 8 + ch;
        *(uint4*)(smem + SOFF_QH + so) = qh[gi];
        *(uint4*)(smem + SOFF_KH + so) = kh[gi];
    }
}
__device__ __forceinline__ void stage4(char* smem, size_t base, int i0, int j0, int t) {
    const uint4* qh = (const uint4*)(g_qh + (base + i0) * Dc);
    const uint4* ql = (const uint4*)(g_ql + (base + i0) * Dc);
    const uint4* kh = (const uint4*)(g_kh + (base + j0) * Dc);
    const uint4* kl = (const uint4*)(g_kl + (base + j0) * Dc);
#pragma unroll
    for (int it = 0; it < 4; it++) {
        int idx = t + 256 * it;
        int row = idx >> 3, ch = idx & 7;
        uint32_t so = (row * TROW + ch * 8) * 2;
        int gi = row * 8 + ch;
        *(uint4*)(smem + OFF_QH + so) = qh[gi];
        *(uint4*)(smem + OFF_QL + so) = ql[gi];
        *(uint4*)(smem + OFF_KH + so) = kh[gi];
        *(uint4*)(smem + OFF_KL + so) = kl[gi];
    }
}

// One N-half GEMM, NPASS in {1,3}. acc[4][2][4] = 32 regs live.
template <int NPASS>
__device__ __forceinline__ void compute_half(uint32_t aHi, uint32_t aLo,
                                             uint32_t bHi, uint32_t bLo,
                                             int wm, int wn, int half,
                                             int lane, float acc[4][2][4]) {
#pragma unroll
    for (int mt = 0; mt < 4; mt++)
#pragma unroll
        for (int nt = 0; nt < 2; nt++)
#pragma unroll
            for (int e = 0; e < 4; e++) acc[mt][nt][e] = 0.f;

    const int a_row = (lane & 7) + ((lane >> 3) & 1) * 8;
    const int a_colb = (lane >> 4) * 8;
    const int b_row = lane & 7;
    const int b_colb = ((lane >> 3) & 1) * 8;
    const int ncol0 = wn * 32 + half * 16;

    const uint32_t aBases[3] = { aHi, aLo, aHi };
    const uint32_t bBases[3] = { bHi, bHi, bLo };

#pragma unroll
    for (int pass = 0; pass < NPASS; pass++) {
        const uint32_t aB = aBases[pass], bB = bBases[pass];
#pragma unroll
        for (int ks = 0; ks < 4; ks++) {
            uint32_t a[4][4], b[2][2];
#pragma unroll
            for (int mt = 0; mt < 4; mt++) {
                uint32_t addr = aB +
                    ((wm * 64 + mt * 16 + a_row) * TROW + ks * 16 + a_colb) * 2;
                ldsm_x4(addr, a[mt][0], a[mt][1], a[mt][2], a[mt][3]);
            }
#pragma unroll
            for (int nt = 0; nt < 2; nt++) {
                uint32_t addr = bB +
                    ((ncol0 + nt * 8 + b_row) * TROW + ks * 16 + b_colb) * 2;
                ldsm_x2(addr, b[nt][0], b[nt][1]);
            }
#pragma unroll
            for (int mt = 0; mt < 4; mt++)
#pragma unroll
                for (int nt = 0; nt < 2; nt++)
                    mma_bf16(acc[mt][nt], a[mt], b[nt]);
        }
    }
}

// triangular decode p -> (a, b), b <= a
__device__ __forceinline__ void tri_decode(int p, int& a, int& b) {
    a = (int)((sqrtf(8.0f * (float)p + 1.0f) - 1.0f) * 0.5f);
    while ((a + 1) * (a + 2) / 2 <= p) a++;
    while (a * (a + 1) / 2 > p) a--;
    b = p - a * (a + 1) / 2;
}

// ---------------------------------------------------------------------------
// Pass A: row sums, hi-only GEMM. 2 smem tiles, 3 CTAs/SM. Uniform diag branch.
// ---------------------------------------------------------------------------
__global__ __launch_bounds__(256, 3) void sums_kernel() {
    extern __shared__ char smem[];
    const uint32_t sb = smem_u32(smem);
    const int t = threadIdx.x, wid = t >> 5, lane = t & 31;

    int qt, kt;
    tri_decode(blockIdx.x, qt, kt);
    const bool diag = (kt == qt);
    const int bh = blockIdx.y;
    const int i0 = qt * 128, j0 = kt * 128;
    const size_t base = (size_t)bh * Sc;

    stage2(smem, base, i0, j0, t);
    __syncthreads();

    const int wm = wid >> 2, wn = wid & 3;
    const int qrow = lane >> 2;
    const int cpair = (lane & 3) * 2;

    float rs0[4], rs1[4];
#pragma unroll
    for (int mt = 0; mt < 4; mt++) { rs0[mt] = 0.f; rs1[mt] = 0.f; }

#pragma unroll
    for (int half = 0; half < 2; half++) {
        float acc[4][2][4];
        compute_half<1>(sb + SOFF_QH, 0u, sb + SOFF_KH, 0u, wm, wn, half, lane, acc);
        if (!diag) {
#pragma unroll
            for (int mt = 0; mt < 4; mt++)
#pragma unroll
                for (int nt = 0; nt < 2; nt++) {
                    float* d = acc[mt][nt];
                    rs0[mt] += ex2f(d[0]) + ex2f(d[1]);
                    rs1[mt] += ex2f(d[2]) + ex2f(d[3]);
                }
        } else {
#pragma unroll
            for (int mt = 0; mt < 4; mt++) {
                const int r0l = wm * 64 + mt * 16 + qrow;
                const int r1l = r0l + 8;
#pragma unroll
                for (int nt = 0; nt < 2; nt++) {
                    const int c = wn * 32 + half * 16 + nt * 8 + cpair;
                    float* d = acc[mt][nt];
                    if (c <= r0l)     rs0[mt] += ex2f(d[0]);
                    if (c + 1 <= r0l) rs0[mt] += ex2f(d[1]);
                    if (c <= r1l)     rs1[mt] += ex2f(d[2]);
                    if (c + 1 <= r1l) rs1[mt] += ex2f(d[3]);
                }
            }
        }
    }

#pragma unroll
    for (int mt = 0; mt < 4; mt++) {
        const int r0l = wm * 64 + mt * 16 + qrow;
        float s0 = rs0[mt], s1 = rs1[mt];
        s0 += __shfl_xor_sync(0xffffffffu, s0, 1);
        s0 += __shfl_xor_sync(0xffffffffu, s0, 2);
        s1 += __shfl_xor_sync(0xffffffffu, s1, 1);
        s1 += __shfl_xor_sync(0xffffffffu, s1, 2);
        if ((lane & 3) == 0) {
            atomicAdd(&g_rowsum[base + i0 + r0l], s0);
            atomicAdd(&g_rowsum[base + i0 + r0l + 8], s1);
        }
    }
}

// ---------------------------------------------------------------------------
// zfin: invZ per row + write the sink column of out.
// ---------------------------------------------------------------------------
__global__ __launch_bounds__(256) void zfin_kernel(const float* __restrict__ sinks,
                                                   float* __restrict__ out) {
    int row = blockIdx.x * blockDim.x + threadIdx.x;
    if (row >= NROWS) return;
    const int i = row & (Sc - 1);
    const float es = __expf(sinks[row]);
    const float invZ = 1.0f / (g_rowsum[row] + (float)(Sc - 1 - i) + es);
    g_invz[row] = invZ;
    out[(size_t)row * SP1 + Sc] = es * invZ;
}

// ---------------------------------------------------------------------------
// Fill kernel: strictly-masked tiles (kt > qt), out = invZ.
// ---------------------------------------------------------------------------
__global__ __launch_bounds__(256) void fill_kernel(float* __restrict__ out) {
    int a, b;
    tri_decode(blockIdx.x, a, b);
    const int kt = a + 1;
    const int qt = b;
    const int bh = blockIdx.y;
    const int i0 = qt * 128, j0 = kt * 128;
    const size_t base = (size_t)bh * Sc;
    const int wid = threadIdx.x >> 5, lane = threadIdx.x & 31;

#pragma unroll
    for (int rr = 0; rr < 16; rr++) {
        const int r = wid * 16 + rr;
        const size_t rowg = base + i0 + r;
        const float invZ = g_invz[rowg];
        const size_t g0 = rowg * SP1 + j0;
        float* rp = out + g0;
        const int a0 = ((int)(4 - (g0 & 3))) & 3;
        const int nvec = (128 - a0) >> 2;
        if (lane < a0) stcs(rp + lane, invZ);
        if (lane < nvec) stcs4(rp + a0 + 4 * lane, invZ);
        if (lane == 31 && a0) {
#pragma unroll
            for (int ti = 0; ti < 3; ti++)
                if (ti < 4 - a0) stcs(rp + a0 + 124 + ti, invZ);
        }
    }
}

// ---------------------------------------------------------------------------
// Pass B: causal tiles. Full 3-pass GEMM, direct fragment stores, 2 CTAs/SM
// (best-known R12 config). Uniform diag branch on the epilogue.
// ---------------------------------------------------------------------------
__global__ __launch_bounds__(256, 2) void write_kernel(float* __restrict__ out) {
    extern __shared__ char smem[];
    const uint32_t sb = smem_u32(smem);
    const int t = threadIdx.x, wid = t >> 5, lane = t & 31;

    int qt, kt;
    tri_decode(blockIdx.x, qt, kt);
    const bool diag = (kt == qt);
    const int bh = blockIdx.y;
    const int i0 = qt * 128, j0 = kt * 128;
    const size_t base = (size_t)bh * Sc;

    stage4(smem, base, i0, j0, t);
    __syncthreads();

    const int wm = wid >> 2, wn = wid & 3;
    const int qrow = lane >> 2;
    const int cpair = (lane & 3) * 2;

#pragma unroll
    for (int half = 0; half < 2; half++) {
        float acc[4][2][4];
        compute_half<3>(sb + OFF_QH, sb + OFF_QL, sb + OFF_KH, sb + OFF_KL,
                        wm, wn, half, lane, acc);
#pragma unroll
        for (int mt = 0; mt < 4; mt++) {
            const int r0l = wm * 64 + mt * 16 + qrow;
            const int r1l = r0l + 8;
            const float iz0 = g_invz[base + i0 + r0l];
            const float iz1 = g_invz[base + i0 + r1l];
            float* orow0 = out + (base + (size_t)(i0 + r0l)) * SP1 + j0;
            float* orow1 = out + (base + (size_t)(i0 + r1l)) * SP1 + j0;
            if (!diag) {
#pragma unroll
                for (int nt = 0; nt < 2; nt++) {
                    const int c = wn * 32 + half * 16 + nt * 8 + cpair;
                    float* d = acc[mt][nt];
                    stcs(orow0 + c,     ex2f(d[0]) * iz0);
                    stcs(orow0 + c + 1, ex2f(d[1]) * iz0);
                    stcs(orow1 + c,     ex2f(d[2]) * iz1);
                    stcs(orow1 + c + 1, ex2f(d[3]) * iz1);
                }
            } else {
#pragma unroll
                for (int nt = 0; nt < 2; nt++) {
                    const int c = wn * 32 + half * 16 + nt * 8 + cpair;
                    float* d = acc[mt][nt];
                    stcs(orow0 + c,     (c <= r0l)     ? ex2f(d[0]) * iz0 : iz0);
                    stcs(orow0 + c + 1, (c + 1 <= r0l) ? ex2f(d[1]) * iz0 : iz0);
                    stcs(orow1 + c,     (c <= r1l)     ? ex2f(d[2]) * iz1 : iz1);
                    stcs(orow1 + c + 1, (c + 1 <= r1l) ? ex2f(d[3]) * iz1 : iz1);
                }
            }
        }
    }
}

// ---------------------------------------------------------------------------
extern "C" void kernel_launch(void* const* d_in, const int* in_sizes, int n_in,
                              void* d_out, int out_size) {
    const float* q     = (const float*)d_in[0];
    const float* k     = (const float*)d_in[1];
    const float* sinks = (const float*)d_in[2];
    float* out = (float*)d_out;
    (void)in_sizes; (void)n_in; (void)out_size;

    cudaFuncSetAttribute(sums_kernel, cudaFuncAttributeMaxDynamicSharedMemorySize, SMEM_S);
    cudaFuncSetAttribute(write_kernel, cudaFuncAttributeMaxDynamicSharedMemorySize, SMEM_W);

    prep2_kernel<<<NROWS / 16, 256>>>(q, k);
    sums_kernel<<<dim3(NT128, Bc * Hc), 256, SMEM_S>>>();
    zfin_kernel<<<NROWS / 256, 256>>>(sinks, out);
    fill_kernel<<<dim3(NFILL, Bc * Hc), 256>>>(out);
    write_kernel<<<dim3(NT128, Bc * Hc), 256, SMEM_W>>>(out);
}